// round 1
// baseline (speedup 1.0000x reference)
#include <cuda_runtime.h>

// Problem constants (from reference)
#define VOCAB   512
#define MAXLEN  512
#define BATCH   128
#define NFEAT   (VOCAB + VOCAB * VOCAB + 2)   // 262658

// One CTA per batch row. Threads cooperatively:
//  1) load x[b, :, :] as float2 (action, time), stash action ids in smem,
//     fold a masked max over times,
//  2) gather-reduce W[a_j] + W[V + a_j*V + a_{j+1}] over valid positions,
//  3) tree-reduce (sum, max) and write out[b].
__global__ __launch_bounds__(256, 8)
void lr_ngram_kernel(const float* __restrict__ x,
                     const int*   __restrict__ lengths,
                     const float* __restrict__ W,
                     const float* __restrict__ bias,
                     float*       __restrict__ out)
{
    __shared__ int   s_act[MAXLEN];
    __shared__ float s_sum[8];
    __shared__ float s_max[8];

    const int b   = blockIdx.x;
    const int tid = threadIdx.x;
    const int len = lengths[b];

    const float2* __restrict__ xrow =
        reinterpret_cast<const float2*>(x + (size_t)b * MAXLEN * 2);

    // Phase 1: load row, cache action ids, masked time max.
    float tmax = -3.402823466e38f;
    #pragma unroll
    for (int j = tid; j < MAXLEN; j += 256) {
        float2 at = xrow[j];               // .x = action (as float), .y = time
        s_act[j] = (int)at.x;
        if (j < len) tmax = fmaxf(tmax, at.y);
    }
    __syncthreads();

    // Phase 2: gather-reduce against W.
    float sum = 0.0f;
    #pragma unroll
    for (int j = tid; j < MAXLEN; j += 256) {
        if (j < len) {
            int a = s_act[j];
            sum += W[a];                                   // unigram
            if (j + 1 < len)
                sum += W[VOCAB + a * VOCAB + s_act[j + 1]]; // bigram
        }
    }

    // Phase 3: block reduction (8 warps).
    const unsigned m = 0xffffffffu;
    #pragma unroll
    for (int off = 16; off > 0; off >>= 1) {
        sum  += __shfl_down_sync(m, sum, off);
        tmax  = fmaxf(tmax, __shfl_down_sync(m, tmax, off));
    }
    const int lane = tid & 31, wid = tid >> 5;
    if (lane == 0) { s_sum[wid] = sum; s_max[wid] = tmax; }
    __syncthreads();

    if (wid == 0) {
        sum  = (lane < 8) ? s_sum[lane] : 0.0f;
        tmax = (lane < 8) ? s_max[lane] : -3.402823466e38f;
        #pragma unroll
        for (int off = 4; off > 0; off >>= 1) {
            sum  += __shfl_down_sync(m, sum, off);
            tmax  = fmaxf(tmax, __shfl_down_sync(m, tmax, off));
        }
        if (lane == 0) {
            // lengths >= 1 always (per setup), so tmax is valid.
            out[b] = sum
                   + tmax * W[NFEAT - 2]
                   + (float)len * W[NFEAT - 1]
                   + bias[0];
        }
    }
}

extern "C" void kernel_launch(void* const* d_in, const int* in_sizes, int n_in,
                              void* d_out, int out_size)
{
    const float* x       = (const float*)d_in[0];   // [B, MAXLEN, 2] f32
    const int*   lengths = (const int*)  d_in[1];   // [B] i32
    const float* W       = (const float*)d_in[2];   // [1, F] f32
    const float* bias    = (const float*)d_in[3];   // [1] f32
    float*       out     = (float*)d_out;           // [B, 1] f32

    lr_ngram_kernel<<<BATCH, 256>>>(x, lengths, W, bias, out);
}

// round 2
// speedup vs baseline: 1.0750x; 1.0750x over previous
#include <cuda_runtime.h>

// Problem constants (from reference)
#define VOCAB   512
#define MAXLEN  512
#define BATCH   128
#define NFEAT   (VOCAB + VOCAB * VOCAB + 2)   // 262658

// One CTA per batch row, 512 threads, one sequence position per thread.
// No smem staging: neighbor action comes from __shfl_down_sync (consecutive
// thread->position mapping); lane 31 loads its neighbor directly.
// Maximizes outstanding gathers per SM (16 warps x ~3 front-batched LDGs).
__global__ __launch_bounds__(512, 2)
void lr_ngram_kernel(const float* __restrict__ x,
                     const int*   __restrict__ lengths,
                     const float* __restrict__ W,
                     const float* __restrict__ bias,
                     float*       __restrict__ out)
{
    __shared__ float s_sum[16];
    __shared__ float s_max[16];

    const int b    = blockIdx.x;
    const int j    = threadIdx.x;          // position, 0..511
    const int lane = j & 31;
    const int wid  = j >> 5;
    const int len  = lengths[b];

    const float2* __restrict__ xrow =
        reinterpret_cast<const float2*>(x + (size_t)b * MAXLEN * 2);

    // Load this position's (action, time).
    float2 at = xrow[j];
    int a = (int)at.x;

    // Neighbor action a_{j+1}: intra-warp shuffle; warp boundary loads directly.
    int anext = __shfl_down_sync(0xffffffffu, a, 1);
    if (lane == 31 && j + 1 < MAXLEN)
        anext = (int)xrow[j + 1].x;

    // Gather-reduce. Both loads independent; issue together.
    float sum = 0.0f;
    if (j < len)       sum += W[a];                                  // unigram
    if (j + 1 < len)   sum += W[VOCAB + (a << 9) + anext];           // bigram

    float tmax = (j < len) ? at.y : -3.402823466e38f;

    // Warp reduction.
    const unsigned m = 0xffffffffu;
    #pragma unroll
    for (int off = 16; off > 0; off >>= 1) {
        sum  += __shfl_down_sync(m, sum, off);
        tmax  = fmaxf(tmax, __shfl_down_sync(m, tmax, off));
    }
    if (lane == 0) { s_sum[wid] = sum; s_max[wid] = tmax; }
    __syncthreads();

    // Final reduction across 16 warps, done by warp 0.
    if (wid == 0) {
        sum  = (lane < 16) ? s_sum[lane] : 0.0f;
        tmax = (lane < 16) ? s_max[lane] : -3.402823466e38f;
        #pragma unroll
        for (int off = 8; off > 0; off >>= 1) {
            sum  += __shfl_down_sync(m, sum, off);
            tmax  = fmaxf(tmax, __shfl_down_sync(m, tmax, off));
        }
        if (lane == 0) {
            out[b] = sum
                   + tmax * W[NFEAT - 2]
                   + (float)len * W[NFEAT - 1]
                   + bias[0];
        }
    }
}

extern "C" void kernel_launch(void* const* d_in, const int* in_sizes, int n_in,
                              void* d_out, int out_size)
{
    const float* x       = (const float*)d_in[0];   // [B, MAXLEN, 2] f32
    const int*   lengths = (const int*)  d_in[1];   // [B] i32
    const float* W       = (const float*)d_in[2];   // [1, F] f32
    const float* bias    = (const float*)d_in[3];   // [1] f32
    float*       out     = (float*)d_out;           // [B, 1] f32

    lr_ngram_kernel<<<BATCH, 512>>>(x, lengths, W, bias, out);
}